// round 7
// baseline (speedup 1.0000x reference)
#include <cuda_runtime.h>
#include <cstdint>

#define OUTD 11008
#define IND  4096
#define GCNT 704512
#define CDIM 172
#define NB   8
#define ICHUNK 512
#define NIT  8                      /* 64 groups per iter (2 per lane) */

typedef unsigned long long ull;
typedef unsigned int u32;

// ---------------------------------------------------------------------------
__global__ void init_out_kernel(const float* __restrict__ bias,
                                float* __restrict__ out) {
    int idx = blockIdx.x * blockDim.x + threadIdx.x;
    if (idx < NB * OUTD) out[idx] = bias[idx % OUTD];
}

// packed f32x2 helpers (sm_100+)
__device__ __forceinline__ void fma2(ull& acc, ull a, ull b) {
    asm("fma.rn.f32x2 %0, %1, %2, %0;" : "+l"(acc) : "l"(a), "l"(b));
}
__device__ __forceinline__ ull fma2d(ull a, ull b, ull c) {
    ull r; asm("fma.rn.f32x2 %0, %1, %2, %3;" : "=l"(r) : "l"(a), "l"(b), "l"(c)); return r;
}
__device__ __forceinline__ ull add2(ull a, ull b) {
    ull r; asm("add.rn.f32x2 %0, %1, %2;" : "=l"(r) : "l"(a), "l"(b)); return r;
}
__device__ __forceinline__ ull pack2(float v) {
    ull r; asm("mov.b64 %0, {%1, %1};" : "=l"(r) : "f"(v)); return r;
}
__device__ __forceinline__ ull pack2f(float a, float b) {
    ull r; asm("mov.b64 %0, {%1, %2};" : "=l"(r) : "f"(a), "f"(b)); return r;
}
__device__ __forceinline__ ull pack2u(u32 a, u32 b) {
    ull r; asm("mov.b64 %0, {%1, %2};" : "=l"(r) : "r"(a), "r"(b)); return r;
}

// ---------------------------------------------------------------------------
// Block = (c, i-chunk of 512). Warp w owns Wq rows 4w..4w+3 (=> 8 output rows
// via hi/lo nibble pairs). Lane covers 2 consecutive groups per iter (int2).
// Weights are dequantized directly into f32x2 pairs {w_lo, w_hi}; x is staged
// pre-duplicated {x,x} in smem so every MAC is one fma.rn.f32x2, no MOVs.
// ---------------------------------------------------------------------------
__global__ __launch_bounds__(256, 2) void hqq_gemv_kernel(
    const int*   __restrict__ Wq,     // [32, 704512] int32 (one byte per elem)
    const float* __restrict__ scale,  // [704512]
    const float* __restrict__ zero,   // [704512]
    const float* __restrict__ x,      // [8, 4096]
    float*       __restrict__ out)    // [8, 11008]
{
    __shared__ ull xsm[NB * ICHUNK];                   // 32 KB: xdup[b][j']

    const int tid = threadIdx.x;
    const int h   = blockIdx.x & 7;                    // i-chunk
    const int c   = blockIdx.x >> 3;                   // 0..171
    const int ib  = h * ICHUNK;

    // Stage x duplicated: pos(b,j) = b*512 + (j&1)*256 + (j>>1)
    // so lane l at iter it, sub k reads pos = b*512 + k*256 + it*32 + l
    // (consecutive lanes -> consecutive ull -> conflict-free LDS.64).
    for (int k = tid; k < NB * ICHUNK; k += 256) {
        int b = k >> 9, j = k & (ICHUNK - 1);
        float v = x[b * IND + ib + j];
        xsm[(b << 9) + ((j & 1) << 8) + (j >> 1)] = pack2(v);
    }
    __syncthreads();

    const int w    = tid >> 5;                         // warp 0..7
    const int l    = tid & 31;
    const int wrow = w << 2;                           // Wq rows wrow..wrow+3
    const int hg0  = (c * IND + ib) >> 1;              // int2/float2 index base

    const int2*   qp0 = (const int2*)(Wq + (long)(wrow + 0) * GCNT) + hg0 + l;
    const int2*   qp1 = (const int2*)(Wq + (long)(wrow + 1) * GCNT) + hg0 + l;
    const int2*   qp2 = (const int2*)(Wq + (long)(wrow + 2) * GCNT) + hg0 + l;
    const int2*   qp3 = (const int2*)(Wq + (long)(wrow + 3) * GCNT) + hg0 + l;
    const float2* sp  = (const float2*)scale + hg0 + l;
    const float2* zp  = (const float2*)zero  + hg0 + l;

    const ull csub = pack2(-8388608.f);                // {-2^23, -2^23}

    ull acc[32];                                       // acc[r*8+b] = {lo,hi}
    #pragma unroll
    for (int i = 0; i < 32; ++i) acc[i] = 0ull;

    #pragma unroll 2
    for (int it = 0; it < NIT; ++it) {
        const int2   qa = __ldg(qp0 + it * 32);
        const int2   qb = __ldg(qp1 + it * 32);
        const int2   qc = __ldg(qp2 + it * 32);
        const int2   qd = __ldg(qp3 + it * 32);
        const float2 s2 = __ldg(sp  + it * 32);
        const float2 z2 = __ldg(zp  + it * 32);

        #pragma unroll
        for (int k = 0; k < 2; ++k) {
            const float s  = k ? s2.y : s2.x;
            const float z  = k ? z2.y : z2.x;
            const ull  sv  = pack2f(s, s * 0.0625f);   // {s, s/16} exact pow2
            const ull  tv  = pack2(-z * s);            // {t, t}

            const ull* xr = xsm + (k << 8) + it * 32 + l;
            const ull xb0 = xr[0],        xb1 = xr[512],  xb2 = xr[1024], xb3 = xr[1536];
            const ull xb4 = xr[2048],     xb5 = xr[2560], xb6 = xr[3072], xb7 = xr[3584];

            // pair-dequant: f = {nl, 16*nh} exact; w = {nl*s+t, 16nh*(s/16)+t}
#define DOROW(QV, R)                                                            \
            {                                                                   \
                u32 vlo = ((u32)(QV) & 0x0Fu) | 0x4B000000u;                    \
                u32 vhi = ((u32)(QV) & 0xF0u) | 0x4B000000u;                    \
                ull wv = fma2d(add2(pack2u(vlo, vhi), csub), sv, tv);           \
                fma2(acc[(R)*8 + 0], xb0, wv); fma2(acc[(R)*8 + 1], xb1, wv);   \
                fma2(acc[(R)*8 + 2], xb2, wv); fma2(acc[(R)*8 + 3], xb3, wv);   \
                fma2(acc[(R)*8 + 4], xb4, wv); fma2(acc[(R)*8 + 5], xb5, wv);   \
                fma2(acc[(R)*8 + 6], xb6, wv); fma2(acc[(R)*8 + 7], xb7, wv);   \
            }
            DOROW(k ? qa.y : qa.x, 0)
            DOROW(k ? qb.y : qb.x, 1)
            DOROW(k ? qc.y : qc.x, 2)
            DOROW(k ? qd.y : qd.x, 3)
#undef DOROW
        }
    }

    // Butterfly halving exchange: 32 f32x2 items -> lane l holds item l summed
    // over all 32 lanes. item k: r = k>>3 (warp-local row), b = k&7 (batch).
    #pragma unroll
    for (int d = 16; d >= 1; d >>= 1) {
        const bool up = (l & d) != 0;
        #pragma unroll
        for (int k = 0; k < d; ++k) {
            ull send = up ? acc[k] : acc[k + d];
            ull got  = __shfl_xor_sync(0xffffffffu, send, d);
            ull keep = up ? acc[k + d] : acc[k];
            acc[k] = add2(keep, got);
        }
    }

    float flo, fhi;                                    // lo-nibble / hi-nibble sums
    asm("mov.b64 {%0, %1}, %2;" : "=f"(flo), "=f"(fhi) : "l"(acc[0]));
    const int r = l >> 3, b = l & 7;
    const int o_hi = (wrow + r)      * CDIM + c;
    const int o_lo = (wrow + r + 32) * CDIM + c;
    atomicAdd(out + b * OUTD + o_hi, fhi);
    atomicAdd(out + b * OUTD + o_lo, flo);
}

// ---------------------------------------------------------------------------
extern "C" void kernel_launch(void* const* d_in, const int* in_sizes, int n_in,
                              void* d_out, int out_size) {
    const int*   Wq    = (const int*)  d_in[0];
    const float* scale = (const float*)d_in[1];
    const float* zero  = (const float*)d_in[2];
    const float* x     = (const float*)d_in[3];
    const float* bias  = (const float*)d_in[4];
    float* out = (float*)d_out;

    init_out_kernel<<<(NB * OUTD + 255) / 256, 256>>>(bias, out);
    hqq_gemv_kernel<<<CDIM * (IND / ICHUNK), 256>>>(Wq, scale, zero, x, out);
}

// round 8
// speedup vs baseline: 1.3865x; 1.3865x over previous
#include <cuda_runtime.h>
#include <cstdint>

#define OUTD 11008
#define IND  4096
#define GCNT 704512
#define CDIM 172
#define NB   8
#define ICHUNK 512
#define NIT  4                      /* 128 groups per iter (4 per lane, int4) */

typedef unsigned long long ull;

// ---------------------------------------------------------------------------
__global__ void init_out_kernel(const float* __restrict__ bias,
                                float* __restrict__ out) {
    int idx = blockIdx.x * blockDim.x + threadIdx.x;
    if (idx < NB * OUTD) out[idx] = bias[idx % OUTD];
}

// packed f32x2 helpers (sm_100+)
__device__ __forceinline__ void fma2(ull& acc, ull a, ull b) {
    asm("fma.rn.f32x2 %0, %1, %2, %0;" : "+l"(acc) : "l"(a), "l"(b));
}
__device__ __forceinline__ ull add2(ull a, ull b) {
    ull r; asm("add.rn.f32x2 %0, %1, %2;" : "=l"(r) : "l"(a), "l"(b)); return r;
}
__device__ __forceinline__ ull pack2(float v) {
    ull r; asm("mov.b64 %0, {%1, %1};" : "=l"(r) : "f"(v)); return r;
}
__device__ __forceinline__ ull pack2f(float a, float b) {
    ull r; asm("mov.b64 %0, {%1, %2};" : "=l"(r) : "f"(a), "f"(b)); return r;
}

// ---------------------------------------------------------------------------
// Block = (c, i-chunk of 512). Warp w owns Wq rows 4w..4w+3 (8 output rows via
// hi/lo nibbles). Lane owns 4 CONSECUTIVE groups per iter -> all global loads
// are LDG.128 (int4 / float4): 4x fewer load instrs, 4x bytes in flight.
// ---------------------------------------------------------------------------
__global__ __launch_bounds__(256, 2) void hqq_gemv_kernel(
    const int*   __restrict__ Wq,     // [32, 704512] int32 (one byte per elem)
    const float* __restrict__ scale,  // [704512]
    const float* __restrict__ zero,   // [704512]
    const float* __restrict__ x,      // [8, 4096]
    float*       __restrict__ out)    // [8, 11008]
{
    // x pair-planes: plane p = (j&3)*4 + bp holds {x[2bp][j], x[2bp+1][j]}
    // at index j>>2. Lane l, iter it, substep jo, pair bp reads
    // xsm[((jo*4)+bp)*128 + it*32 + l] -> lane-consecutive, conflict-free.
    __shared__ ull xsm[16 * 128];                      // 16 KB

    const int tid = threadIdx.x;
    const int h   = blockIdx.x & 7;                    // i-chunk
    const int c   = blockIdx.x >> 3;                   // 0..171
    const int ib  = h * ICHUNK;

    for (int k = tid; k < 4 * ICHUNK; k += 256) {      // 2048 entries
        int bp = k >> 9, j = k & (ICHUNK - 1);
        float lo = x[(2 * bp)     * IND + ib + j];
        float hi = x[(2 * bp + 1) * IND + ib + j];
        xsm[((j & 3) * 4 + bp) * 128 + (j >> 2)] = pack2f(lo, hi);
    }
    __syncthreads();

    const int w    = tid >> 5;                         // warp 0..7
    const int l    = tid & 31;
    const int wrow = w << 2;                           // Wq rows wrow..wrow+3
    const int g0   = c * IND + ib;                     // stripe base (16B-aligned)

    const int4*   qp0 = (const int4*)(Wq + (long)(wrow + 0) * GCNT + g0) + l;
    const int4*   qp1 = (const int4*)(Wq + (long)(wrow + 1) * GCNT + g0) + l;
    const int4*   qp2 = (const int4*)(Wq + (long)(wrow + 2) * GCNT + g0) + l;
    const int4*   qp3 = (const int4*)(Wq + (long)(wrow + 3) * GCNT + g0) + l;
    const float4* sp  = (const float4*)(scale + g0) + l;
    const float4* zp  = (const float4*)(zero  + g0) + l;

    ull acc[32];                                       // [rp*8 + 0..3]=hi, 4..7=lo
    #pragma unroll
    for (int i = 0; i < 32; ++i) acc[i] = 0ull;

    // prefetch iter 0 (6x LDG.128)
    int4   qa = __ldg(qp0), qb = __ldg(qp1), qc = __ldg(qp2), qd = __ldg(qp3);
    float4 s4 = __ldg(sp),  z4 = __ldg(zp);

    #pragma unroll
    for (int it = 0; it < NIT; ++it) {
        // prefetch next stripe (last iter: in-bounds re-read of stripe 0)
        const int off = (it + 1 < NIT) ? (it + 1) * 32 : 0;
        int4   qan = __ldg(qp0 + off), qbn = __ldg(qp1 + off);
        int4   qcn = __ldg(qp2 + off), qdn = __ldg(qp3 + off);
        float4 s4n = __ldg(sp + off),  z4n = __ldg(zp + off);

        const int   qra[4] = {qa.x, qa.y, qa.z, qa.w};
        const int   qrb[4] = {qb.x, qb.y, qb.z, qb.w};
        const int   qrc[4] = {qc.x, qc.y, qc.z, qc.w};
        const int   qrd[4] = {qd.x, qd.y, qd.z, qd.w};
        const float sa[4]  = {s4.x, s4.y, s4.z, s4.w};
        const float za[4]  = {z4.x, z4.y, z4.z, z4.w};

        #pragma unroll
        for (int jo = 0; jo < 4; ++jo) {               // substep = one group
            const float s   = sa[jo];
            const float t   = -za[jo] * s;             // small magnitude
            const float s16 = s * 0.0625f;             // exact pow2

            const ull* xr = xsm + (jo * 4) * 128 + it * 32 + l;
            const ull x01 = xr[0], x23 = xr[128], x45 = xr[256], x67 = xr[384];

            // Exact nibble extraction, then one rounding FMA (R3 numerics).
#define DOROW(QV, RP)                                                          \
            {                                                                  \
                float fl = __int_as_float(((QV) & 0x0F) | 0x4B000000) - 8388608.f; \
                float fh = __int_as_float(((QV) & 0xF0) | 0x4B000000) - 8388608.f; \
                float wl = fmaf(fl, s, t);                                     \
                float wh = fmaf(fh, s16, t);                                   \
                ull wh2 = pack2(wh), wl2 = pack2(wl);                          \
                fma2(acc[(RP)*8 + 0], x01, wh2); fma2(acc[(RP)*8 + 1], x23, wh2); \
                fma2(acc[(RP)*8 + 2], x45, wh2); fma2(acc[(RP)*8 + 3], x67, wh2); \
                fma2(acc[(RP)*8 + 4], x01, wl2); fma2(acc[(RP)*8 + 5], x23, wl2); \
                fma2(acc[(RP)*8 + 6], x45, wl2); fma2(acc[(RP)*8 + 7], x67, wl2); \
            }
            DOROW(qra[jo], 0) DOROW(qrb[jo], 1) DOROW(qrc[jo], 2) DOROW(qrd[jo], 3)
#undef DOROW
        }

        qa = qan; qb = qbn; qc = qcn; qd = qdn; s4 = s4n; z4 = z4n;
    }

    // Butterfly halving exchange: 32 f32x2 per lane -> lane l holds item l
    // summed over all 32 lanes. item k: rp=k>>3, half=(k>>2)&1, pair=k&3.
    #pragma unroll
    for (int d = 16; d >= 1; d >>= 1) {
        const bool up = (l & d) != 0;
        #pragma unroll
        for (int k = 0; k < d; ++k) {
            ull send = up ? acc[k] : acc[k + d];
            ull got  = __shfl_xor_sync(0xffffffffu, send, d);
            ull keep = up ? acc[k + d] : acc[k];
            acc[k] = add2(keep, got);
        }
    }

    float fx, fy;
    asm("mov.b64 {%0, %1}, %2;" : "=f"(fx), "=f"(fy) : "l"(acc[0]));
    const int rp = l >> 3, half = (l >> 2) & 1, pair = l & 3;
    const int o  = (wrow + rp + half * 32) * CDIM + c;
    atomicAdd(out + (2 * pair)     * OUTD + o, fx);
    atomicAdd(out + (2 * pair + 1) * OUTD + o, fy);
}

// ---------------------------------------------------------------------------
extern "C" void kernel_launch(void* const* d_in, const int* in_sizes, int n_in,
                              void* d_out, int out_size) {
    const int*   Wq    = (const int*)  d_in[0];
    const float* scale = (const float*)d_in[1];
    const float* zero  = (const float*)d_in[2];
    const float* x     = (const float*)d_in[3];
    const float* bias  = (const float*)d_in[4];
    float* out = (float*)d_out;

    init_out_kernel<<<(NB * OUTD + 255) / 256, 256>>>(bias, out);
    hqq_gemv_kernel<<<CDIM * (IND / ICHUNK), 256>>>(Wq, scale, zero, x, out);
}